// round 6
// baseline (speedup 1.0000x reference)
#include <cuda_runtime.h>
#include <cuda_bf16.h>
#include <cstdint>

#define Bc   8
#define CCc  512
#define Kc   64
#define Vc   256
#define Tc   1024
#define KSc  23
#define EPSc 1e-5f
#define BKV  (Bc * Kc * Vc)

typedef unsigned long long u64t;

#define PACK2(d, v)  asm("mov.b64 %0, {%1, %1};" : "=l"(d) : "f"(v))
#define FMA2(d, a, b) asm("fma.rn.f32x2 %0, %1, %2, %0;" : "+l"(d) : "l"(a), "l"(b))
#define UNPACK2(lo, hi, in) asm("mov.b64 {%0, %1}, %2;" : "=f"(lo), "=f"(hi) : "l"(in))

#define MMA16816(d, a, b)                                                    \
    asm volatile(                                                            \
        "mma.sync.aligned.m16n8k16.row.col.f32.bf16.bf16.f32 "               \
        "{%0,%1,%2,%3}, {%4,%5,%6,%7}, {%8,%9}, {%0,%1,%2,%3};"              \
        : "+f"((d)[0]), "+f"((d)[1]), "+f"((d)[2]), "+f"((d)[3])             \
        : "r"((a)[0]), "r"((a)[1]), "r"((a)[2]), "r"((a)[3]),                \
          "r"((b)[0]), "r"((b)[1]))

// ---------------- scratch (device globals) ----------------
__device__ float g_Q[Bc * Kc * Tc];       // raw queries
__device__ float g_K[Bc * Kc * Tc];       // keys -> softmaxed in place
__device__ float g_V[Bc * Vc * Tc];       // raw values
__device__ float g_CLp[4 * BKV];          // split-T partials of content lambda
__device__ float g_CL[BKV];               // content lambda (BN(V) folded in)
__device__ float g_qpos[Bc * Tc * KSc];   // qn @ pos_w
__device__ float g_qb[Bc * Tc];           // qn @ pos_b
__device__ float g_qsc[Kc], g_qof[Kc];    // BN(Q) affine
__device__ float g_vsc[Vc], g_vof[Vc];    // BN(V) affine

__device__ __forceinline__ uint32_t pack_bf2(float lo, float hi) {
    __nv_bfloat162 h = __floats2bfloat162_rn(lo, hi);
    return *reinterpret_cast<uint32_t*>(&h);
}

// ---------------- tensor-core Q/K/V projection (mma.sync bf16, 3-pass split) --
// C[b][m][t] = sum_c W[m][c]*X[b][c][t] + bias[m]
// Block: 64m x 128t, 256 threads (8 warps, each m32 x n32), BK=32.
// z: [0,8) Q, [8,16) K, [16,48) V (b=zz>>2, m0=(zz&3)*64)
__global__ void __launch_bounds__(256, 2)
proj_mma(const float* __restrict__ x, const float* __restrict__ ctx,
         const float* __restrict__ Wq, const float* __restrict__ bq,
         const float* __restrict__ Wk, const float* __restrict__ bk,
         const float* __restrict__ Wv, const float* __restrict__ bv,
         float* __restrict__ Qd, float* __restrict__ Kd, float* __restrict__ Vd)
{
    const int z = blockIdx.z;
    const float *W, *Xb, *bias;
    float* C;
    int b, m0;
    if (z < 8)        { b = z;      m0 = 0;            W = Wq; bias = bq; Xb = x;   C = Qd + (size_t)b * Kc * Tc; }
    else if (z < 16)  { b = z - 8;  m0 = 0;            W = Wk; bias = bk; Xb = ctx; C = Kd + (size_t)b * Kc * Tc; }
    else { int zz = z - 16; b = zz >> 2; m0 = (zz & 3) * 64; W = Wv; bias = bv; Xb = ctx; C = Vd + (size_t)b * Vc * Tc; }
    const float* X = Xb + (size_t)b * CCc * Tc;
    const int t0 = blockIdx.x * 128;

    // padded stride 40 bf16 per row -> conflict-free fragment loads
    __shared__ __nv_bfloat16 Ahs[64 * 40], Als[64 * 40];
    __shared__ __nv_bfloat16 Bhs[128 * 40], Bls[128 * 40];

    const int tid  = threadIdx.x;
    const int lane = tid & 31;
    const int warp = tid >> 5;
    const int wm = (warp & 1) * 32;
    const int wn = (warp >> 1) * 32;

    float acc[2][4][4];
#pragma unroll
    for (int i = 0; i < 2; i++)
#pragma unroll
        for (int j = 0; j < 4; j++)
#pragma unroll
            for (int q = 0; q < 4; q++) acc[i][j][q] = 0.f;

    for (int ch = 0; ch < 16; ch++) {
        const int c0 = ch * 32;
        // ---- W slice [64m][32c] -> Ah/Al ----
#pragma unroll
        for (int f = tid; f < 512; f += 256) {
            int m = f >> 3, c4 = f & 7;
            float4 w = *reinterpret_cast<const float4*>(&W[(size_t)(m0 + m) * CCc + c0 + c4 * 4]);
            float hx = __bfloat162float(__float2bfloat16_rn(w.x));
            float hy = __bfloat162float(__float2bfloat16_rn(w.y));
            float hz = __bfloat162float(__float2bfloat16_rn(w.z));
            float hw = __bfloat162float(__float2bfloat16_rn(w.w));
            uint32_t* ah = reinterpret_cast<uint32_t*>(&Ahs[m * 40 + c4 * 4]);
            uint32_t* al = reinterpret_cast<uint32_t*>(&Als[m * 40 + c4 * 4]);
            ah[0] = pack_bf2(hx, hy);
            ah[1] = pack_bf2(hz, hw);
            al[0] = pack_bf2(w.x - hx, w.y - hy);
            al[1] = pack_bf2(w.z - hz, w.w - hw);
        }
        // ---- X slice [32c][128t] -> Bh/Bl transposed to [t][c] ----
        {
            int c = tid >> 3, tq = tid & 7;
            const float* xp = &X[(size_t)(c0 + c) * Tc + t0 + tq * 16];
#pragma unroll
            for (int j = 0; j < 4; j++) {
                float4 xv = *reinterpret_cast<const float4*>(&xp[j * 4]);
                int tb = tq * 16 + j * 4;
                float e[4] = {xv.x, xv.y, xv.z, xv.w};
#pragma unroll
                for (int q = 0; q < 4; q++) {
                    __nv_bfloat16 h = __float2bfloat16_rn(e[q]);
                    Bhs[(tb + q) * 40 + c] = h;
                    Bls[(tb + q) * 40 + c] = __float2bfloat16_rn(e[q] - __bfloat162float(h));
                }
            }
        }
        __syncthreads();

        // ---- MMA: 2 k16-steps x (2m x 4n tiles) x 3 passes ----
#pragma unroll
        for (int kk = 0; kk < 32; kk += 16) {
            const int kb = kk + (lane & 3) * 2;
            uint32_t ah[2][4], al[2][4], bh[4][2], bl[4][2];
#pragma unroll
            for (int mt = 0; mt < 2; mt++) {
                int r = wm + mt * 16 + (lane >> 2);
                ah[mt][0] = *reinterpret_cast<uint32_t*>(&Ahs[r * 40 + kb]);
                ah[mt][1] = *reinterpret_cast<uint32_t*>(&Ahs[(r + 8) * 40 + kb]);
                ah[mt][2] = *reinterpret_cast<uint32_t*>(&Ahs[r * 40 + kb + 8]);
                ah[mt][3] = *reinterpret_cast<uint32_t*>(&Ahs[(r + 8) * 40 + kb + 8]);
                al[mt][0] = *reinterpret_cast<uint32_t*>(&Als[r * 40 + kb]);
                al[mt][1] = *reinterpret_cast<uint32_t*>(&Als[(r + 8) * 40 + kb]);
                al[mt][2] = *reinterpret_cast<uint32_t*>(&Als[r * 40 + kb + 8]);
                al[mt][3] = *reinterpret_cast<uint32_t*>(&Als[(r + 8) * 40 + kb + 8]);
            }
#pragma unroll
            for (int nt = 0; nt < 4; nt++) {
                int cidx = wn + nt * 8 + (lane >> 2);
                bh[nt][0] = *reinterpret_cast<uint32_t*>(&Bhs[cidx * 40 + kb]);
                bh[nt][1] = *reinterpret_cast<uint32_t*>(&Bhs[cidx * 40 + kb + 8]);
                bl[nt][0] = *reinterpret_cast<uint32_t*>(&Bls[cidx * 40 + kb]);
                bl[nt][1] = *reinterpret_cast<uint32_t*>(&Bls[cidx * 40 + kb + 8]);
            }
#pragma unroll
            for (int mt = 0; mt < 2; mt++)
#pragma unroll
                for (int nt = 0; nt < 4; nt++) {
                    MMA16816(acc[mt][nt], ah[mt], bh[nt]);
                    MMA16816(acc[mt][nt], ah[mt], bl[nt]);
                    MMA16816(acc[mt][nt], al[mt], bh[nt]);
                }
        }
        __syncthreads();
    }

    // ---- epilogue: bias + store ----
#pragma unroll
    for (int mt = 0; mt < 2; mt++) {
        int r = wm + mt * 16 + (lane >> 2);
        float bi0 = bias[m0 + r];
        float bi8 = bias[m0 + r + 8];
#pragma unroll
        for (int nt = 0; nt < 4; nt++) {
            int cc = wn + nt * 8 + (lane & 3) * 2;
            float2 v0 = {acc[mt][nt][0] + bi0, acc[mt][nt][1] + bi0};
            float2 v1 = {acc[mt][nt][2] + bi8, acc[mt][nt][3] + bi8};
            *reinterpret_cast<float2*>(&C[(size_t)(m0 + r) * Tc + t0 + cc]) = v0;
            *reinterpret_cast<float2*>(&C[(size_t)(m0 + r + 8) * Tc + t0 + cc]) = v1;
        }
    }
}

// ---------------- fused normalize: softmax(K) in place + BN stats for Q,V ----
__global__ void normalize(float* __restrict__ Kd, const float* __restrict__ Qd,
                          const float* __restrict__ Vd,
                          const float* __restrict__ gq, const float* __restrict__ bq,
                          const float* __restrict__ gv, const float* __restrict__ bv,
                          float* __restrict__ qsc, float* __restrict__ qof,
                          float* __restrict__ vsc, float* __restrict__ vof)
{
    const int tid = threadIdx.x;
    __shared__ float rs[256], rq[256];

    if (blockIdx.x < 512) {
        float* r = Kd + (size_t)blockIdx.x * Tc;
        float v[4];
        float m = -1e30f;
#pragma unroll
        for (int j = 0; j < 4; j++) { v[j] = r[tid + j * 256]; m = fmaxf(m, v[j]); }
        rs[tid] = m; __syncthreads();
        for (int s = 128; s > 0; s >>= 1) {
            if (tid < s) rs[tid] = fmaxf(rs[tid], rs[tid + s]);
            __syncthreads();
        }
        m = rs[0]; __syncthreads();
        float sum = 0.f;
#pragma unroll
        for (int j = 0; j < 4; j++) { v[j] = expf(v[j] - m); sum += v[j]; }
        rs[tid] = sum; __syncthreads();
        for (int s = 128; s > 0; s >>= 1) {
            if (tid < s) rs[tid] += rs[tid + s];
            __syncthreads();
        }
        float inv = 1.f / rs[0];
#pragma unroll
        for (int j = 0; j < 4; j++) r[tid + j * 256] = v[j] * inv;
        return;
    }

    const float* data;
    const float *gamma, *beta;
    float *osc, *oof;
    int c, C;
    if (blockIdx.x < 576) { c = blockIdx.x - 512; C = Kc; data = Qd; gamma = gq; beta = bq; osc = qsc; oof = qof; }
    else                  { c = blockIdx.x - 576; C = Vc; data = Vd; gamma = gv; beta = bv; osc = vsc; oof = vof; }

    float s = 0.f, sq = 0.f;
    for (int i = tid; i < Bc * Tc; i += 256) {
        int b = i >> 10, t = i & 1023;
        float z = data[((size_t)b * C + c) * Tc + t];
        s += z; sq += z * z;
    }
    rs[tid] = s; rq[tid] = sq; __syncthreads();
    for (int st = 128; st > 0; st >>= 1) {
        if (tid < st) { rs[tid] += rs[tid + st]; rq[tid] += rq[tid + st]; }
        __syncthreads();
    }
    if (tid == 0) {
        const float invN = 1.f / (Bc * Tc);
        float mean = rs[0] * invN;
        float var  = rq[0] * invN - mean * mean;
        float g  = gamma[c] * rsqrtf(var + EPSc);
        osc[c] = g;
        oof[c] = beta[c] - mean * g;
    }
}

// ---------------- mid kernel: cl_part (blocks 0..127) + qpos (blocks 128..255)
__global__ void mid_kernel(const float* __restrict__ Kn, const float* __restrict__ Vr,
                           float* __restrict__ CLp,
                           const float* __restrict__ Qr, const float* __restrict__ pos_w,
                           const float* __restrict__ pos_b,
                           const float* __restrict__ qsc, const float* __restrict__ qof,
                           float* __restrict__ qpos, float* __restrict__ qb)
{
    __shared__ float smem[5728];
    const int tid = threadIdx.x;   // 256

    if (blockIdx.x < 128) {
        const int xid = blockIdx.x;
        const int v0 = (xid & 3) * 64;
        const int b  = (xid >> 2) & 7;
        const int ts = xid >> 5;
        const float* Ab = Kn + (size_t)b * Kc * Tc;
        const float* Vb = Vr + (size_t)b * Vc * Tc;

        float* As = smem;            // [32][65]
        float* Bs = smem + 2080;     // [32][65]

        float acc[4][4];
#pragma unroll
        for (int i = 0; i < 4; i++)
#pragma unroll
            for (int j = 0; j < 4; j++) acc[i][j] = 0.f;

        const int tr = tid / 16, tc = tid % 16;

        for (int t0 = ts * 256; t0 < ts * 256 + 256; t0 += 32) {
#pragma unroll
            for (int i = tid; i < 64 * 32; i += 256) {
                int r = i / 32, tt = i % 32;
                As[tt * 65 + r] = Ab[(size_t)r * Tc + t0 + tt];
                Bs[tt * 65 + r] = Vb[(size_t)(v0 + r) * Tc + t0 + tt];
            }
            __syncthreads();
#pragma unroll
            for (int tt = 0; tt < 32; tt++) {
                float a[4], bb[4];
#pragma unroll
                for (int i = 0; i < 4; i++) a[i] = As[tt * 65 + tr * 4 + i];
#pragma unroll
                for (int j = 0; j < 4; j++) bb[j] = Bs[tt * 65 + tc * 4 + j];
#pragma unroll
                for (int i = 0; i < 4; i++)
#pragma unroll
                    for (int j = 0; j < 4; j++) acc[i][j] += a[i] * bb[j];
            }
            __syncthreads();
        }
        float* Cb = CLp + (size_t)ts * BKV + (size_t)b * Kc * Vc;
#pragma unroll
        for (int i = 0; i < 4; i++)
#pragma unroll
            for (int j = 0; j < 4; j++)
                Cb[(size_t)(tr * 4 + i) * Vc + v0 + tc * 4 + j] = acc[i][j];
    } else {
        const int idx = blockIdx.x - 128;
        const int t0 = (idx & 15) * 64;
        const int b  = idx >> 4;

        float* Qs  = smem;                      // [64][65]
        float* pws = smem + 64 * 65;            // [64][24]
        float* cs  = smem + 64 * 65 + 64 * 24;  // [24]

        for (int i = tid; i < 64 * 64; i += 256) {
            int k = i >> 6, t = i & 63;
            Qs[k * 65 + t] = Qr[((size_t)b * Kc + k) * Tc + t0 + t];
        }
        for (int i = tid; i < Kc * KSc; i += 256) {
            int k = i / KSc, s = i % KSc;
            pws[k * 24 + s] = qsc[k] * pos_w[k * KSc + s];
        }
        if (tid < Kc) pws[tid * 24 + 23] = qsc[tid] * pos_b[tid];
        if (tid < 24) {
            float c = 0.f;
            if (tid < 23) {
                for (int k = 0; k < Kc; k++) c += qof[k] * pos_w[k * KSc + tid];
            } else {
                for (int k = 0; k < Kc; k++) c += qof[k] * pos_b[k];
            }
            cs[tid] = c;
        }
        __syncthreads();

        const int t  = tid & 63;
        const int sg = tid >> 6;

        float acc[6];
#pragma unroll
        for (int j = 0; j < 6; j++) acc[j] = cs[sg * 6 + j];

#pragma unroll 8
        for (int k = 0; k < Kc; k++) {
            float q = Qs[k * 65 + t];
#pragma unroll
            for (int j = 0; j < 6; j++) acc[j] += q * pws[k * 24 + sg * 6 + j];
        }
#pragma unroll
        for (int j = 0; j < 6; j++) {
            int slot = sg * 6 + j;
            if (slot < 23) qpos[((size_t)b * Tc + t0 + t) * KSc + slot] = acc[j];
            else           qb[(size_t)b * Tc + t0 + t] = acc[j];
        }
    }
}

// CL = vsc[v]*(sum of 4 partials) + vof[v]
__global__ void cl_reduce(const float* __restrict__ CLp, float* __restrict__ CL,
                          const float* __restrict__ vsc, const float* __restrict__ vof)
{
    int i = blockIdx.x * 256 + threadIdx.x;
    int v = i & (Vc - 1);
    float s = CLp[i] + CLp[i + BKV] + CLp[i + 2 * BKV] + CLp[i + 3 * BKV];
    CL[i] = s * vsc[v] + vof[v];
}

// ---------------- fused output (content part in f32x2) ----------------
__global__ void out_kernel(const float* __restrict__ Qr, const float* __restrict__ CL,
                           const float* __restrict__ Vr, const float* __restrict__ qpos,
                           const float* __restrict__ qb,
                           const float* __restrict__ qsc, const float* __restrict__ qof,
                           const float* __restrict__ vsc, const float* __restrict__ vof,
                           float* __restrict__ out)
{
    const int b  = blockIdx.z;
    const int v0 = blockIdx.y * 32;
    const int t0 = blockIdx.x * 64;
    const int tid = threadIdx.x;
    const int tl = tid & 63;
    const int vlane = tid >> 6;

    __shared__ float Qs[64][64];
    __shared__ float cls[64][32];
    __shared__ float qps[64][25];
    __shared__ float Vs[32][86];
    __shared__ float qsS[64], qoS[64], vsS[32], voS[32];

    if (tid < 64) { qsS[tid] = qsc[tid]; qoS[tid] = qof[tid]; }
    else if (tid < 96)  { vsS[tid - 64] = vsc[v0 + tid - 64]; }
    else if (tid < 128) { voS[tid - 96] = vof[v0 + tid - 96]; }
    __syncthreads();

#pragma unroll 4
    for (int i = tid; i < 64 * 64; i += 256) {
        int k = i >> 6, t = i & 63;
        Qs[k][t] = Qr[((size_t)b * Kc + k) * Tc + t0 + t] * qsS[k] + qoS[k];
    }
#pragma unroll 2
    for (int i = tid; i < 64 * 32; i += 256) {
        int k = i >> 5, vv = i & 31;
        cls[k][vv] = CL[((size_t)b * Kc + k) * Vc + v0 + vv];
    }
    for (int i = tid; i < 64 * KSc; i += 256) {
        int t = i / KSc, s = i % KSc;
        qps[t][s] = qpos[((size_t)b * Tc + t0 + t) * KSc + s];
    }
    if (tid < 64) qps[tid][23] = qb[b * Tc + t0 + tid];
    for (int i = tid; i < 32 * 86; i += 256) {
        int vv = i / 86, idx = i % 86;
        int tg = t0 - 11 + idx;
        Vs[vv][idx] = (tg >= 0 && tg < Tc)
                          ? Vr[((size_t)b * Vc + v0 + vv) * Tc + tg] * vsS[vv] + voS[vv]
                          : 0.f;
    }
    __syncthreads();

    u64t accp[4];
#pragma unroll
    for (int q = 0; q < 4; q++) accp[q] = 0ULL;

#pragma unroll
    for (int k = 0; k < Kc; k++) {
        u64t qv;
        PACK2(qv, Qs[k][tl]);
        const u64t* cp = reinterpret_cast<const u64t*>(&cls[k][vlane * 8]);
#pragma unroll
        for (int q = 0; q < 4; q++) FMA2(accp[q], qv, cp[q]);
    }

    float acc[8];
#pragma unroll
    for (int q = 0; q < 4; q++) UNPACK2(acc[2 * q], acc[2 * q + 1], accp[q]);

#pragma unroll
    for (int s = 0; s < KSc; s++) {
        float qp = qps[tl][s];
#pragma unroll
        for (int j = 0; j < 8; j++) acc[j] += qp * Vs[vlane * 8 + j][tl + s];
    }
    float qbv = qps[tl][23];
#pragma unroll
    for (int j = 0; j < 8; j++)
        out[((size_t)b * Vc + v0 + vlane * 8 + j) * Tc + t0 + tl] = acc[j] + qbv;
}

// ---------------- launch ----------------
extern "C" void kernel_launch(void* const* d_in, const int* in_sizes, int n_in,
                              void* d_out, int out_size)
{
    const float* x       = (const float*)d_in[0];
    const float* context = (const float*)d_in[1];
    const float* Wq      = (const float*)d_in[2];
    const float* bq      = (const float*)d_in[3];
    const float* Wk      = (const float*)d_in[4];
    const float* bk      = (const float*)d_in[5];
    const float* Wv      = (const float*)d_in[6];
    const float* bv      = (const float*)d_in[7];
    const float* gamma_q = (const float*)d_in[8];
    const float* beta_q  = (const float*)d_in[9];
    const float* gamma_v = (const float*)d_in[10];
    const float* beta_v  = (const float*)d_in[11];
    const float* pos_w   = (const float*)d_in[12];
    const float* pos_b   = (const float*)d_in[13];
    float* out = (float*)d_out;

    float *dQ, *dK, *dV, *dCLp, *dCL, *dqp, *dqb, *dqsc, *dqof, *dvsc, *dvof;
    cudaGetSymbolAddress((void**)&dQ,   g_Q);
    cudaGetSymbolAddress((void**)&dK,   g_K);
    cudaGetSymbolAddress((void**)&dV,   g_V);
    cudaGetSymbolAddress((void**)&dCLp, g_CLp);
    cudaGetSymbolAddress((void**)&dCL,  g_CL);
    cudaGetSymbolAddress((void**)&dqp,  g_qpos);
    cudaGetSymbolAddress((void**)&dqb,  g_qb);
    cudaGetSymbolAddress((void**)&dqsc, g_qsc);
    cudaGetSymbolAddress((void**)&dqof, g_qof);
    cudaGetSymbolAddress((void**)&dvsc, g_vsc);
    cudaGetSymbolAddress((void**)&dvof, g_vof);

    proj_mma<<<dim3(Tc / 128, 1, 48), 256>>>(x, context, Wq, bq, Wk, bk, Wv, bv,
                                             dQ, dK, dV);
    normalize<<<832, 256>>>(dK, dQ, dV, gamma_q, beta_q, gamma_v, beta_v,
                            dqsc, dqof, dvsc, dvof);
    mid_kernel<<<256, 256>>>(dK, dV, dCLp, dQ, pos_w, pos_b, dqsc, dqof, dqp, dqb);
    cl_reduce<<<BKV / 256, 256>>>(dCLp, dCL, dvsc, dvof);
    out_kernel<<<dim3(Tc / 64, Vc / 32, Bc), 256>>>(dQ, dCL, dV, dqp, dqb,
                                                    dqsc, dqof, dvsc, dvof, out);
}